// round 5
// baseline (speedup 1.0000x reference)
#include <cuda_runtime.h>
#include <cuda_fp16.h>
#include <math.h>

#define NN 50000
#define EE 1600000
#define TOT (EE + NN)
#define HC 128
#define NEG_SLOPE 0.2f
#define NCHUNK 49        // ceil(50000/1024)
#define G_GEMM 782       // ceil(50000/64)

// ---------------- scratch ----------------
__device__ __half g_xh[NN * HC];       // fp16 projected features (gather source)
__device__ float  g_as[NN * 2];
__device__ float  g_ad[NN * 2];
__device__ int    g_counts[NN];        // zero-initialized; self-resetting (scan2 zeroes after read)
__device__ int    g_offsets[NN + 1];
__device__ int    g_cursor[NN];
__device__ int    g_ssrc[TOT];
__device__ int    g_bsum[NCHUNK];

// ---------------- 1) histogram of dst (int4 loads; counts start at 0) ------
__global__ void k_hist(const int* __restrict__ ei) {
    int t = blockIdx.x * blockDim.x + threadIdx.x;
    if (t < EE / 4) {
        int4 d = ((const int4*)(ei + EE))[t];
        atomicAdd(&g_counts[d.x], 1);
        atomicAdd(&g_counts[d.y], 1);
        atomicAdd(&g_counts[d.z], 1);
        atomicAdd(&g_counts[d.w], 1);
    }
}

// ---------------- 2a) chunk sums (self-loop +1 folded in) ----------------
__global__ void k_chunksum() {
    __shared__ int ws[8];
    int b = blockIdx.x;
    int base = b * 1024;
    int sum = 0;
    for (int i = threadIdx.x; i < 1024; i += 256) {
        int idx = base + i;
        if (idx < NN) sum += g_counts[idx] + 1;   // +1 self loop
    }
    #pragma unroll
    for (int d = 16; d >= 1; d >>= 1) sum += __shfl_xor_sync(0xffffffffu, sum, d);
    int lane = threadIdx.x & 31, wid = threadIdx.x >> 5;
    if (lane == 0) ws[wid] = sum;
    __syncthreads();
    if (threadIdx.x == 0) {
        int s = 0;
        #pragma unroll
        for (int i = 0; i < 8; i++) s += ws[i];
        g_bsum[b] = s;
    }
}

// ---------------- 2b) per-chunk scan; zeroes counts for next replay --------
__global__ void k_scan2() {
    __shared__ int s_pref[64];
    __shared__ int s_total;
    __shared__ int warp_sums[32];
    int b = blockIdx.x;
    int tid = threadIdx.x, lane = tid & 31, wid = tid >> 5;

    if (wid == 0) {
        int v0 = (lane < NCHUNK) ? g_bsum[lane] : 0;
        int v1 = (32 + lane < NCHUNK) ? g_bsum[32 + lane] : 0;
        int x = v0;
        #pragma unroll
        for (int d = 1; d < 32; d <<= 1) {
            int t = __shfl_up_sync(0xffffffffu, x, d);
            if (lane >= d) x += t;
        }
        int tot0 = __shfl_sync(0xffffffffu, x, 31);
        int y = v1;
        #pragma unroll
        for (int d = 1; d < 32; d <<= 1) {
            int t = __shfl_up_sync(0xffffffffu, y, d);
            if (lane >= d) y += t;
        }
        s_pref[lane] = x - v0;
        s_pref[32 + lane] = tot0 + y - v1;
        if (lane == 31) s_total = tot0 + y;
    }
    __syncthreads();
    int prev = s_pref[b];

    int i = b * 1024 + tid;
    int v = 0;
    if (i < NN) {
        v = g_counts[i] + 1;       // +1 self loop
        g_counts[i] = 0;           // reset for next graph replay
    }
    int x = v;
    #pragma unroll
    for (int d = 1; d < 32; d <<= 1) {
        int t = __shfl_up_sync(0xffffffffu, x, d);
        if (lane >= d) x += t;
    }
    if (lane == 31) warp_sums[wid] = x;
    __syncthreads();
    if (wid == 0) {
        int s = warp_sums[lane];
        #pragma unroll
        for (int d = 1; d < 32; d <<= 1) {
            int t = __shfl_up_sync(0xffffffffu, s, d);
            if (lane >= d) s += t;
        }
        warp_sums[lane] = s;
    }
    __syncthreads();
    int excl = (wid ? warp_sums[wid - 1] : 0) + x - v;
    if (i < NN) {
        int off = prev + excl;
        g_offsets[i] = off;
        g_cursor[i] = off;
    }
    if (b == 0 && tid == 0) g_offsets[NN] = s_total;
}

// ---------------- 3) fused GEMM(+attn, fp16 out) and CSR scatter -----------
__global__ void k_gemm_scatter(const float* __restrict__ A, const float* __restrict__ W,
                               const float* __restrict__ att_src,
                               const float* __restrict__ att_dst,
                               const int* __restrict__ ei) {
    __shared__ __align__(16) float As[128 * 66];

    if (blockIdx.x >= G_GEMM) {
        // -------- scatter branch --------
        int t = (blockIdx.x - G_GEMM) * blockDim.x + threadIdx.x;
        const int EQ = EE / 4;
        if (t < EQ) {
            int4 s = ((const int4*)ei)[t];
            int4 d = ((const int4*)(ei + EE))[t];
            int p;
            p = atomicAdd(&g_cursor[d.x], 1); g_ssrc[p] = s.x;
            p = atomicAdd(&g_cursor[d.y], 1); g_ssrc[p] = s.y;
            p = atomicAdd(&g_cursor[d.z], 1); g_ssrc[p] = s.z;
            p = atomicAdd(&g_cursor[d.w], 1); g_ssrc[p] = s.w;
        } else if (t - EQ < NN) {
            int n = t - EQ;
            int p = atomicAdd(&g_cursor[n], 1);
            g_ssrc[p] = n;
        }
        return;
    }

    // -------- GEMM branch --------
    int tid = threadIdx.x;
    int tc = tid & 31;
    int tr = tid >> 5;
    int row0 = blockIdx.x * 64;

    const float4* Ag = (const float4*)A;
    for (int i = tid; i < 64 * 32; i += 256) {
        int r = i >> 5, kq = i & 31;
        int row = row0 + r;
        float4 v = (row < NN) ? Ag[(size_t)row * 32 + kq] : make_float4(0.f, 0.f, 0.f, 0.f);
        As[(4 * kq + 0) * 66 + r] = v.x;
        As[(4 * kq + 1) * 66 + r] = v.y;
        As[(4 * kq + 2) * 66 + r] = v.z;
        As[(4 * kq + 3) * 66 + r] = v.w;
    }
    __syncthreads();

    unsigned long long acc[4][4];
    #pragma unroll
    for (int r = 0; r < 4; r++)
        #pragma unroll
        for (int c = 0; c < 4; c++) acc[r][c] = 0ull;

    const float4* Wg = (const float4*)W;
    int rbase = tr * 8;

    #pragma unroll 4
    for (int k = 0; k < 128; k++) {
        float4 w4 = __ldg(&Wg[k * 32 + tc]);
        unsigned long long ww[4];
        asm("mov.b64 %0, {%1, %1};" : "=l"(ww[0]) : "f"(w4.x));
        asm("mov.b64 %0, {%1, %1};" : "=l"(ww[1]) : "f"(w4.y));
        asm("mov.b64 %0, {%1, %1};" : "=l"(ww[2]) : "f"(w4.z));
        asm("mov.b64 %0, {%1, %1};" : "=l"(ww[3]) : "f"(w4.w));
        unsigned long long ap[4];
        #pragma unroll
        for (int r = 0; r < 4; r++) {
            float2 a2 = *(const float2*)&As[k * 66 + rbase + 2 * r];
            asm("mov.b64 %0, {%1, %2};" : "=l"(ap[r]) : "f"(a2.x), "f"(a2.y));
        }
        #pragma unroll
        for (int r = 0; r < 4; r++)
            #pragma unroll
            for (int c = 0; c < 4; c++)
                asm("fma.rn.f32x2 %0, %1, %2, %0;" : "+l"(acc[r][c]) : "l"(ap[r]), "l"(ww[c]));
    }

    float4 sA4 = ((const float4*)att_src)[tc];
    float4 dA4 = ((const float4*)att_dst)[tc];

    #pragma unroll
    for (int r = 0; r < 4; r++) {
        float lo[4], hi[4];
        #pragma unroll
        for (int c = 0; c < 4; c++)
            asm("mov.b64 {%0, %1}, %2;" : "=f"(lo[c]), "=f"(hi[c]) : "l"(acc[r][c]));
        int rowA = row0 + rbase + 2 * r;
        int rowB = rowA + 1;
        if (rowA < NN) {
            half2 h0 = __floats2half2_rn(lo[0], lo[1]);
            half2 h1 = __floats2half2_rn(lo[2], lo[3]);
            ((uint2*)g_xh)[(size_t)rowA * 32 + tc] =
                make_uint2(*(unsigned*)&h0, *(unsigned*)&h1);
        }
        if (rowB < NN) {
            half2 h0 = __floats2half2_rn(hi[0], hi[1]);
            half2 h1 = __floats2half2_rn(hi[2], hi[3]);
            ((uint2*)g_xh)[(size_t)rowB * 32 + tc] =
                make_uint2(*(unsigned*)&h0, *(unsigned*)&h1);
        }

        float psA = lo[0] * sA4.x + lo[1] * sA4.y + lo[2] * sA4.z + lo[3] * sA4.w;
        float pdA = lo[0] * dA4.x + lo[1] * dA4.y + lo[2] * dA4.z + lo[3] * dA4.w;
        float psB = hi[0] * sA4.x + hi[1] * sA4.y + hi[2] * sA4.z + hi[3] * sA4.w;
        float pdB = hi[0] * dA4.x + hi[1] * dA4.y + hi[2] * dA4.z + hi[3] * dA4.w;
        #pragma unroll
        for (int d = 8; d >= 1; d >>= 1) {
            psA += __shfl_xor_sync(0xffffffffu, psA, d);
            pdA += __shfl_xor_sync(0xffffffffu, pdA, d);
            psB += __shfl_xor_sync(0xffffffffu, psB, d);
            pdB += __shfl_xor_sync(0xffffffffu, pdB, d);
        }
        if ((tc == 0 || tc == 16)) {
            int hh = tc >> 4;
            if (rowA < NN) { g_as[2 * rowA + hh] = psA; g_ad[2 * rowA + hh] = pdA; }
            if (rowB < NN) { g_as[2 * rowB + hh] = psB; g_ad[2 * rowB + hh] = pdB; }
        }
    }
}

// ---------------- 4) single-pass edge softmax + aggregate ------------------
__device__ __forceinline__ float leaky(float x) {
    return x > 0.f ? x : NEG_SLOPE * x;
}

__global__ void k_aggregate(const float* __restrict__ bias, float* __restrict__ out) {
    __shared__ int   s_idx[8][32];
    __shared__ float s_p[8][2][32];

    int w = (blockIdx.x * blockDim.x + threadIdx.x) >> 5;
    if (w >= NN) return;
    int lane = threadIdx.x & 31;
    int h = lane >> 4;
    int ws = (threadIdx.x >> 5) & 7;
    int beg = g_offsets[w], end = g_offsets[w + 1];

    float ad0 = g_ad[2 * w + 0];
    float ad1 = g_ad[2 * w + 1];
    const uint2* xh = (const uint2*)g_xh;

    float den = 0.f;
    float4 acc = make_float4(0.f, 0.f, 0.f, 0.f);

    for (int base = beg; base < end; base += 32) {
        int nb = end - base;                        // may exceed 32; clipped by lane test
        int idx = 0;
        float p0 = 0.f, p1 = 0.f;
        if (lane < nb) {
            idx = g_ssrc[base + lane];
            float2 as2 = *(const float2*)&g_as[2 * idx];
            p0 = __expf(leaky(as2.x + ad0));
            p1 = __expf(leaky(as2.y + ad1));
        }
        s_idx[ws][lane] = idx;
        s_p[ws][0][lane] = p0;
        s_p[ws][1][lane] = p1;
        __syncwarp();

        #pragma unroll 16
        for (int jj = 0; jj < 32; jj++) {
            int s = s_idx[ws][jj];
            float ph = s_p[ws][h][jj];
            uint2 hv = __ldcg(&xh[(size_t)s * 32 + lane]);
            float2 f01 = __half22float2(*(half2*)&hv.x);
            float2 f23 = __half22float2(*(half2*)&hv.y);
            den += ph;
            acc.x += ph * f01.x;
            acc.y += ph * f01.y;
            acc.z += ph * f23.x;
            acc.w += ph * f23.y;
        }
        __syncwarp();
    }

    float inv = 1.0f / den;
    float4 b = ((const float4*)bias)[lane];
    acc.x = acc.x * inv + b.x;
    acc.y = acc.y * inv + b.y;
    acc.z = acc.z * inv + b.z;
    acc.w = acc.w * inv + b.w;
    acc.x = acc.x > 0.f ? acc.x : expm1f(acc.x);
    acc.y = acc.y > 0.f ? acc.y : expm1f(acc.y);
    acc.z = acc.z > 0.f ? acc.z : expm1f(acc.z);
    acc.w = acc.w > 0.f ? acc.w : expm1f(acc.w);
    ((float4*)out)[(size_t)w * 32 + lane] = acc;
}

// ---------------- launch ----------------
extern "C" void kernel_launch(void* const* d_in, const int* in_sizes, int n_in,
                              void* d_out, int out_size) {
    const float* h_node  = (const float*)d_in[0];
    const int*   ei      = (const int*)d_in[1];
    const float* W       = (const float*)d_in[2];
    const float* att_src = (const float*)d_in[3];
    const float* att_dst = (const float*)d_in[4];
    const float* bias    = (const float*)d_in[5];
    float* out = (float*)d_out;

    k_hist<<<(EE / 4 + 255) / 256, 256>>>(ei);
    k_chunksum<<<NCHUNK, 256>>>();
    k_scan2<<<NCHUNK, 1024>>>();
    int scat_blocks = (EE / 4 + NN + 255) / 256;
    k_gemm_scatter<<<G_GEMM + scat_blocks, 256>>>(h_node, W, att_src, att_dst, ei);
    k_aggregate<<<(NN * 32 + 255) / 256, 256>>>(bias, out);
}

// round 6
// speedup vs baseline: 2.4763x; 2.4763x over previous
#include <cuda_runtime.h>
#include <cuda_fp16.h>
#include <math.h>

#define NN 50000
#define EE 1600000
#define TOT (EE + NN)
#define HC 128
#define NEG_SLOPE 0.2f
#define NCHUNK 49        // ceil(50000/1024)
#define G_GEMM 782       // ceil(50000/64)

// ---------------- scratch ----------------
__device__ __half g_xh[NN * HC];       // fp16 projected features (gather source)
__device__ float  g_as[NN * 2];
__device__ float  g_ad[NN * 2];
__device__ int    g_counts[NN];        // zero-init; self-resetting (scan2 zeroes after read)
__device__ int    g_offsets[NN + 1];
__device__ int    g_cursor[NN];
__device__ int    g_ssrc[TOT];
__device__ int    g_bsum[NCHUNK];

// ---------------- 1) histogram of dst (int4 loads; counts start at 0) ------
__global__ void k_hist(const int* __restrict__ ei) {
    int t = blockIdx.x * blockDim.x + threadIdx.x;
    if (t < EE / 4) {
        int4 d = ((const int4*)(ei + EE))[t];
        atomicAdd(&g_counts[d.x], 1);
        atomicAdd(&g_counts[d.y], 1);
        atomicAdd(&g_counts[d.z], 1);
        atomicAdd(&g_counts[d.w], 1);
    }
}

// ---------------- 2a) chunk sums (self-loop +1 folded in) ----------------
__global__ void k_chunksum() {
    __shared__ int ws[8];
    int b = blockIdx.x;
    int base = b * 1024;
    int sum = 0;
    for (int i = threadIdx.x; i < 1024; i += 256) {
        int idx = base + i;
        if (idx < NN) sum += g_counts[idx] + 1;   // +1 self loop
    }
    #pragma unroll
    for (int d = 16; d >= 1; d >>= 1) sum += __shfl_xor_sync(0xffffffffu, sum, d);
    int lane = threadIdx.x & 31, wid = threadIdx.x >> 5;
    if (lane == 0) ws[wid] = sum;
    __syncthreads();
    if (threadIdx.x == 0) {
        int s = 0;
        #pragma unroll
        for (int i = 0; i < 8; i++) s += ws[i];
        g_bsum[b] = s;
    }
}

// ---------------- 2b) per-chunk scan; zeroes counts for next replay --------
__global__ void k_scan2() {
    __shared__ int s_pref[64];
    __shared__ int s_total;
    __shared__ int warp_sums[32];
    int b = blockIdx.x;
    int tid = threadIdx.x, lane = tid & 31, wid = tid >> 5;

    if (wid == 0) {
        int v0 = (lane < NCHUNK) ? g_bsum[lane] : 0;
        int v1 = (32 + lane < NCHUNK) ? g_bsum[32 + lane] : 0;
        int x = v0;
        #pragma unroll
        for (int d = 1; d < 32; d <<= 1) {
            int t = __shfl_up_sync(0xffffffffu, x, d);
            if (lane >= d) x += t;
        }
        int tot0 = __shfl_sync(0xffffffffu, x, 31);
        int y = v1;
        #pragma unroll
        for (int d = 1; d < 32; d <<= 1) {
            int t = __shfl_up_sync(0xffffffffu, y, d);
            if (lane >= d) y += t;
        }
        s_pref[lane] = x - v0;
        s_pref[32 + lane] = tot0 + y - v1;
        if (lane == 31) s_total = tot0 + y;
    }
    __syncthreads();
    int prev = s_pref[b];

    int i = b * 1024 + tid;
    int v = 0;
    if (i < NN) {
        v = g_counts[i] + 1;       // +1 self loop
        g_counts[i] = 0;           // reset for next replay
    }
    int x = v;
    #pragma unroll
    for (int d = 1; d < 32; d <<= 1) {
        int t = __shfl_up_sync(0xffffffffu, x, d);
        if (lane >= d) x += t;
    }
    if (lane == 31) warp_sums[wid] = x;
    __syncthreads();
    if (wid == 0) {
        int s = warp_sums[lane];
        #pragma unroll
        for (int d = 1; d < 32; d <<= 1) {
            int t = __shfl_up_sync(0xffffffffu, s, d);
            if (lane >= d) s += t;
        }
        warp_sums[lane] = s;
    }
    __syncthreads();
    int excl = (wid ? warp_sums[wid - 1] : 0) + x - v;
    if (i < NN) {
        int off = prev + excl;
        g_offsets[i] = off;
        g_cursor[i] = off;
    }
    if (b == 0 && tid == 0) g_offsets[NN] = s_total;
}

// ---------------- 3) fused GEMM(+attn, fp16 out) and CSR scatter -----------
__global__ void k_gemm_scatter(const float* __restrict__ A, const float* __restrict__ W,
                               const float* __restrict__ att_src,
                               const float* __restrict__ att_dst,
                               const int* __restrict__ ei) {
    __shared__ __align__(16) float As[128 * 66];

    if (blockIdx.x >= G_GEMM) {
        // -------- scatter branch --------
        int t = (blockIdx.x - G_GEMM) * blockDim.x + threadIdx.x;
        const int EQ = EE / 4;
        if (t < EQ) {
            int4 s = ((const int4*)ei)[t];
            int4 d = ((const int4*)(ei + EE))[t];
            int p;
            p = atomicAdd(&g_cursor[d.x], 1); g_ssrc[p] = s.x;
            p = atomicAdd(&g_cursor[d.y], 1); g_ssrc[p] = s.y;
            p = atomicAdd(&g_cursor[d.z], 1); g_ssrc[p] = s.z;
            p = atomicAdd(&g_cursor[d.w], 1); g_ssrc[p] = s.w;
        } else if (t - EQ < NN) {
            int n = t - EQ;
            int p = atomicAdd(&g_cursor[n], 1);
            g_ssrc[p] = n;
        }
        return;
    }

    // -------- GEMM branch --------
    int tid = threadIdx.x;
    int tc = tid & 31;
    int tr = tid >> 5;
    int row0 = blockIdx.x * 64;

    const float4* Ag = (const float4*)A;
    for (int i = tid; i < 64 * 32; i += 256) {
        int r = i >> 5, kq = i & 31;
        int row = row0 + r;
        float4 v = (row < NN) ? Ag[(size_t)row * 32 + kq] : make_float4(0.f, 0.f, 0.f, 0.f);
        As[(4 * kq + 0) * 66 + r] = v.x;
        As[(4 * kq + 1) * 66 + r] = v.y;
        As[(4 * kq + 2) * 66 + r] = v.z;
        As[(4 * kq + 3) * 66 + r] = v.w;
    }
    __syncthreads();

    unsigned long long acc[4][4];
    #pragma unroll
    for (int r = 0; r < 4; r++)
        #pragma unroll
        for (int c = 0; c < 4; c++) acc[r][c] = 0ull;

    const float4* Wg = (const float4*)W;
    int rbase = tr * 8;

    #pragma unroll 4
    for (int k = 0; k < 128; k++) {
        float4 w4 = __ldg(&Wg[k * 32 + tc]);
        unsigned long long ww[4];
        asm("mov.b64 %0, {%1, %1};" : "=l"(ww[0]) : "f"(w4.x));
        asm("mov.b64 %0, {%1, %1};" : "=l"(ww[1]) : "f"(w4.y));
        asm("mov.b64 %0, {%1, %1};" : "=l"(ww[2]) : "f"(w4.z));
        asm("mov.b64 %0, {%1, %1};" : "=l"(ww[3]) : "f"(w4.w));
        unsigned long long ap[4];
        #pragma unroll
        for (int r = 0; r < 4; r++) {
            float2 a2 = *(const float2*)&As[k * 66 + rbase + 2 * r];
            asm("mov.b64 %0, {%1, %2};" : "=l"(ap[r]) : "f"(a2.x), "f"(a2.y));
        }
        #pragma unroll
        for (int r = 0; r < 4; r++)
            #pragma unroll
            for (int c = 0; c < 4; c++)
                asm("fma.rn.f32x2 %0, %1, %2, %0;" : "+l"(acc[r][c]) : "l"(ap[r]), "l"(ww[c]));
    }

    float4 sA4 = ((const float4*)att_src)[tc];
    float4 dA4 = ((const float4*)att_dst)[tc];

    #pragma unroll
    for (int r = 0; r < 4; r++) {
        float lo[4], hi[4];
        #pragma unroll
        for (int c = 0; c < 4; c++)
            asm("mov.b64 {%0, %1}, %2;" : "=f"(lo[c]), "=f"(hi[c]) : "l"(acc[r][c]));
        int rowA = row0 + rbase + 2 * r;
        int rowB = rowA + 1;
        if (rowA < NN) {
            half2 h0 = __floats2half2_rn(lo[0], lo[1]);
            half2 h1 = __floats2half2_rn(lo[2], lo[3]);
            ((uint2*)g_xh)[(size_t)rowA * 32 + tc] =
                make_uint2(*(unsigned*)&h0, *(unsigned*)&h1);
        }
        if (rowB < NN) {
            half2 h0 = __floats2half2_rn(hi[0], hi[1]);
            half2 h1 = __floats2half2_rn(hi[2], hi[3]);
            ((uint2*)g_xh)[(size_t)rowB * 32 + tc] =
                make_uint2(*(unsigned*)&h0, *(unsigned*)&h1);
        }

        float psA = lo[0] * sA4.x + lo[1] * sA4.y + lo[2] * sA4.z + lo[3] * sA4.w;
        float pdA = lo[0] * dA4.x + lo[1] * dA4.y + lo[2] * dA4.z + lo[3] * dA4.w;
        float psB = hi[0] * sA4.x + hi[1] * sA4.y + hi[2] * sA4.z + hi[3] * sA4.w;
        float pdB = hi[0] * dA4.x + hi[1] * dA4.y + hi[2] * dA4.z + hi[3] * dA4.w;
        #pragma unroll
        for (int d = 8; d >= 1; d >>= 1) {
            psA += __shfl_xor_sync(0xffffffffu, psA, d);
            pdA += __shfl_xor_sync(0xffffffffu, pdA, d);
            psB += __shfl_xor_sync(0xffffffffu, psB, d);
            pdB += __shfl_xor_sync(0xffffffffu, pdB, d);
        }
        if ((tc == 0 || tc == 16)) {
            int hh = tc >> 4;
            if (rowA < NN) { g_as[2 * rowA + hh] = psA; g_ad[2 * rowA + hh] = pdA; }
            if (rowB < NN) { g_as[2 * rowB + hh] = psB; g_ad[2 * rowB + hh] = pdB; }
        }
    }
}

// ---------------- 4) single-pass edge softmax + aggregate ------------------
// shuffle-broadcast inner loop, plain L1-cached gathers, expf hoisted out.
__device__ __forceinline__ float leaky(float x) {
    return x > 0.f ? x : NEG_SLOPE * x;
}

__global__ void k_aggregate(const float* __restrict__ bias, float* __restrict__ out) {
    int w = (blockIdx.x * blockDim.x + threadIdx.x) >> 5;
    if (w >= NN) return;
    int lane = threadIdx.x & 31;
    int h = lane >> 4;
    int beg = g_offsets[w], end = g_offsets[w + 1];

    float ad0 = g_ad[2 * w + 0];
    float ad1 = g_ad[2 * w + 1];
    const uint2* xh = (const uint2*)g_xh;

    float den = 0.f;
    float4 acc = make_float4(0.f, 0.f, 0.f, 0.f);

    for (int base = beg; base < end; base += 32) {
        int nb = min(32, end - base);
        int idx = 0;
        float p0 = 0.f, p1 = 0.f;
        if (lane < nb) {
            idx = g_ssrc[base + lane];
            float2 as2 = *(const float2*)&g_as[2 * idx];
            p0 = __expf(leaky(as2.x + ad0));
            p1 = __expf(leaky(as2.y + ad1));
        }
        if (nb == 32) {
            #pragma unroll 8
            for (int jj = 0; jj < 32; jj++) {
                int s = __shfl_sync(0xffffffffu, idx, jj);
                float q0 = __shfl_sync(0xffffffffu, p0, jj);
                float q1 = __shfl_sync(0xffffffffu, p1, jj);
                float ph = h ? q1 : q0;
                uint2 hv = xh[(size_t)s * 32 + lane];
                float2 f01 = __half22float2(*(half2*)&hv.x);
                float2 f23 = __half22float2(*(half2*)&hv.y);
                den += ph;
                acc.x += ph * f01.x;
                acc.y += ph * f01.y;
                acc.z += ph * f23.x;
                acc.w += ph * f23.y;
            }
        } else {
            for (int jj = 0; jj < nb; jj++) {
                int s = __shfl_sync(0xffffffffu, idx, jj);
                float q0 = __shfl_sync(0xffffffffu, p0, jj);
                float q1 = __shfl_sync(0xffffffffu, p1, jj);
                float ph = h ? q1 : q0;
                uint2 hv = xh[(size_t)s * 32 + lane];
                float2 f01 = __half22float2(*(half2*)&hv.x);
                float2 f23 = __half22float2(*(half2*)&hv.y);
                den += ph;
                acc.x += ph * f01.x;
                acc.y += ph * f01.y;
                acc.z += ph * f23.x;
                acc.w += ph * f23.y;
            }
        }
    }

    float inv = 1.0f / den;
    float4 b = ((const float4*)bias)[lane];
    acc.x = acc.x * inv + b.x;
    acc.y = acc.y * inv + b.y;
    acc.z = acc.z * inv + b.z;
    acc.w = acc.w * inv + b.w;
    acc.x = acc.x > 0.f ? acc.x : expm1f(acc.x);
    acc.y = acc.y > 0.f ? acc.y : expm1f(acc.y);
    acc.z = acc.z > 0.f ? acc.z : expm1f(acc.z);
    acc.w = acc.w > 0.f ? acc.w : expm1f(acc.w);
    ((float4*)out)[(size_t)w * 32 + lane] = acc;
}

// ---------------- launch ----------------
extern "C" void kernel_launch(void* const* d_in, const int* in_sizes, int n_in,
                              void* d_out, int out_size) {
    const float* h_node  = (const float*)d_in[0];
    const int*   ei      = (const int*)d_in[1];
    const float* W       = (const float*)d_in[2];
    const float* att_src = (const float*)d_in[3];
    const float* att_dst = (const float*)d_in[4];
    const float* bias    = (const float*)d_in[5];
    float* out = (float*)d_out;

    k_hist<<<(EE / 4 + 255) / 256, 256>>>(ei);
    k_chunksum<<<NCHUNK, 256>>>();
    k_scan2<<<NCHUNK, 1024>>>();
    int scat_blocks = (EE / 4 + NN + 255) / 256;
    k_gemm_scatter<<<G_GEMM + scat_blocks, 256>>>(h_node, W, att_src, att_dst, ei);
    k_aggregate<<<(NN * 32 + 255) / 256, 256>>>(bias, out);
}